// round 1
// baseline (speedup 1.0000x reference)
#include <cuda_runtime.h>
#include <cuda_bf16.h>
#include <math.h>

#define DIM   768
#define HEADS 12
#define HD    64
#define WIN   14
#define NTOK  196          // WIN*WIN
#define NWIN  50           // 2 images * 25 windows
#define MROWS 9800         // NWIN*NTOK
#define GROWS 8192         // 2*64*64
#define MLPH  3072
#define QKVN  2304
#define SCALE 0.125f       // 64^-0.5

// -------------------- scratch (device globals; no allocation) ----------------
__device__ float g_xin_ln[MROWS * DIM];     // LN1 output, window-partitioned+padded
__device__ float g_qkv  [MROWS * QKVN];     // qkv per window token
__device__ float g_attn [MROWS * DIM];      // attention output per window token
__device__ float g_xres [GROWS * DIM];      // x + proj(attn)
__device__ float g_h2   [GROWS * DIM];      // LN2 output
__device__ float g_hid  [GROWS * MLPH];     // gelu(fc1)

// -------------------- block reduce (sum, sumsq) ------------------------------
__device__ __forceinline__ void blockReduce2(float& s, float& ss) {
    #pragma unroll
    for (int o = 16; o; o >>= 1) {
        s  += __shfl_xor_sync(0xffffffffu, s,  o);
        ss += __shfl_xor_sync(0xffffffffu, ss, o);
    }
    __shared__ float ra[8], rb[8];
    int warp = threadIdx.x >> 5, lane = threadIdx.x & 31;
    if (lane == 0) { ra[warp] = s; rb[warp] = ss; }
    __syncthreads();
    if (threadIdx.x == 0) {
        float t1 = 0.f, t2 = 0.f;
        #pragma unroll
        for (int i = 0; i < 8; i++) { t1 += ra[i]; t2 += rb[i]; }
        ra[0] = t1; rb[0] = t2;
    }
    __syncthreads();
    s = ra[0]; ss = rb[0];
}

// -------------------- LN1 + window partition (zero pad) ----------------------
__global__ __launch_bounds__(256) void ln1_kernel(
    const float* __restrict__ x, const float* __restrict__ g,
    const float* __restrict__ b, float* __restrict__ out)
{
    int t = blockIdx.x;                 // 0..9799 window token
    int w  = t / NTOK, tk = t % NTOK;
    int img = w / 25, wy = (w % 25) / 5, wx = w % 5;
    int ty = tk / WIN, tx = tk % WIN;
    int y = wy * WIN + ty, xc = wx * WIN + tx;
    float* orow = out + (size_t)t * DIM;
    int tid = threadIdx.x;
    if (y >= 64 || xc >= 64) {
        orow[tid] = 0.f; orow[tid + 256] = 0.f; orow[tid + 512] = 0.f;
        return;
    }
    const float* row = x + (((size_t)img * 64 + y) * 64 + xc) * DIM;
    float v0 = row[tid], v1 = row[tid + 256], v2 = row[tid + 512];
    float s = v0 + v1 + v2, ss = v0 * v0 + v1 * v1 + v2 * v2;
    blockReduce2(s, ss);
    float mean = s * (1.f / DIM);
    float var  = ss * (1.f / DIM) - mean * mean;
    float rstd = rsqrtf(var + 1e-6f);
    orow[tid]       = (v0 - mean) * rstd * g[tid]       + b[tid];
    orow[tid + 256] = (v1 - mean) * rstd * g[tid + 256] + b[tid + 256];
    orow[tid + 512] = (v2 - mean) * rstd * g[tid + 512] + b[tid + 512];
}

// -------------------- LN2 (plain rows) ---------------------------------------
__global__ __launch_bounds__(256) void ln2_kernel(
    const float* __restrict__ xin, const float* __restrict__ g,
    const float* __restrict__ b, float* __restrict__ out)
{
    int t = blockIdx.x;
    const float* row = xin + (size_t)t * DIM;
    float* orow = out + (size_t)t * DIM;
    int tid = threadIdx.x;
    float v0 = row[tid], v1 = row[tid + 256], v2 = row[tid + 512];
    float s = v0 + v1 + v2, ss = v0 * v0 + v1 * v1 + v2 * v2;
    blockReduce2(s, ss);
    float mean = s * (1.f / DIM);
    float var  = ss * (1.f / DIM) - mean * mean;
    float rstd = rsqrtf(var + 1e-6f);
    orow[tid]       = (v0 - mean) * rstd * g[tid]       + b[tid];
    orow[tid + 256] = (v1 - mean) * rstd * g[tid + 256] + b[tid + 256];
    orow[tid + 512] = (v2 - mean) * rstd * g[tid + 512] + b[tid + 512];
}

// -------------------- tiled SGEMM 64x64x16, 256 thr, 4x4/thread -------------
// C[m,n] = A[m,:] @ B[:,n] + bias[n]   (+gelu) (+res[m,n])
// GATHER: output row m (global token) gathers A row via window map.
template<bool GATHER, bool GELU_ACT, bool RES>
__global__ __launch_bounds__(256) void gemm_kernel(
    const float* __restrict__ A, const float* __restrict__ B,
    const float* __restrict__ bias, const float* __restrict__ Rs,
    float* __restrict__ C, int M, int Nn, int K)
{
    __shared__ float As[16][64];
    __shared__ float Bs[16][64];
    const int tid = threadIdx.x;
    const int bm = blockIdx.y << 6, bn = blockIdx.x << 6;

    const int am  = tid >> 2;          // A tile row 0..63
    const int ak  = (tid & 3) << 2;    // A k offset 0,4,8,12
    const int bk  = tid >> 4;          // B tile k row 0..15
    const int bn0 = (tid & 15) << 2;   // B col offset
    const int rm  = (tid >> 4) << 2;   // result row base
    const int rn  = (tid & 15) << 2;   // result col base

    const float* aptr = nullptr;
    {
        int gm = bm + am;
        if (gm < M) {
            int arow = gm;
            if (GATHER) {
                int img = gm >> 12, rem = gm & 4095;
                int y = rem >> 6, xc = rem & 63;
                arow = (img * 25 + (y / WIN) * 5 + (xc / WIN)) * NTOK
                     + (y % WIN) * WIN + (xc % WIN);
            }
            aptr = A + (size_t)arow * K + ak;
        }
    }
    const float* bptr = B + (size_t)bk * Nn + bn + bn0;

    float acc[4][4];
    #pragma unroll
    for (int i = 0; i < 4; i++)
        #pragma unroll
        for (int j = 0; j < 4; j++) acc[i][j] = 0.f;

    for (int k0 = 0; k0 < K; k0 += 16) {
        float4 av = aptr ? *(const float4*)(aptr + k0) : make_float4(0.f, 0.f, 0.f, 0.f);
        float4 bv = *(const float4*)(bptr + (size_t)k0 * Nn);
        As[ak + 0][am] = av.x; As[ak + 1][am] = av.y;
        As[ak + 2][am] = av.z; As[ak + 3][am] = av.w;
        *(float4*)&Bs[bk][bn0] = bv;
        __syncthreads();
        #pragma unroll
        for (int kk = 0; kk < 16; kk++) {
            float4 a = *(const float4*)&As[kk][rm];
            float4 b = *(const float4*)&Bs[kk][rn];
            acc[0][0] += a.x * b.x; acc[0][1] += a.x * b.y; acc[0][2] += a.x * b.z; acc[0][3] += a.x * b.w;
            acc[1][0] += a.y * b.x; acc[1][1] += a.y * b.y; acc[1][2] += a.y * b.z; acc[1][3] += a.y * b.w;
            acc[2][0] += a.z * b.x; acc[2][1] += a.z * b.y; acc[2][2] += a.z * b.z; acc[2][3] += a.z * b.w;
            acc[3][0] += a.w * b.x; acc[3][1] += a.w * b.y; acc[3][2] += a.w * b.z; acc[3][3] += a.w * b.w;
        }
        __syncthreads();
    }

    #pragma unroll
    for (int i = 0; i < 4; i++) {
        int m = bm + rm + i;
        if (m >= M) break;
        float* crow = C + (size_t)m * Nn + bn + rn;
        const float* rrow = RES ? (Rs + (size_t)m * Nn + bn + rn) : nullptr;
        #pragma unroll
        for (int j = 0; j < 4; j++) {
            float v = acc[i][j] + bias[bn + rn + j];
            if (GELU_ACT) v = 0.5f * v * (1.f + erff(v * 0.70710678118654752f));
            if (RES) v += rrow[j];
            crow[j] = v;
        }
    }
}

// -------------------- attention: one CTA per (window, head) ------------------
// smem: K[196][65], V[196][65], qrow[8][64], prow[8][196], rh/rw[8][28]
#define KV_STRIDE 65
#define SM_K   0
#define SM_V   (NTOK * KV_STRIDE)
#define SM_Q   (2 * NTOK * KV_STRIDE)
#define SM_P   (SM_Q + 8 * 64)
#define SM_R   (SM_P + 8 * NTOK)
#define ATTN_SMEM_FLOATS (SM_R + 8 * 28)

__global__ __launch_bounds__(256) void attn_kernel(
    const float* __restrict__ qkv, const float* __restrict__ relh,
    const float* __restrict__ relw, float* __restrict__ outp)
{
    extern __shared__ float sm[];
    float* Ks = sm + SM_K;
    float* Vs = sm + SM_V;

    const int blk = blockIdx.x;
    const int w = blk / HEADS, h = blk % HEADS;
    const float* base = qkv + (size_t)w * NTOK * QKVN;
    const int tid = threadIdx.x, warp = tid >> 5, lane = tid & 31;

    // load K, V for this head
    for (int idx = tid; idx < NTOK * HD; idx += 256) {
        int j = idx >> 6, d = idx & 63;
        const float* src = base + (size_t)j * QKVN + h * HD + d;
        Ks[j * KV_STRIDE + d] = src[DIM];        // k at +768
        Vs[j * KV_STRIDE + d] = src[2 * DIM];    // v at +1536
    }
    __syncthreads();

    float* myq  = sm + SM_Q + warp * 64;
    float* myp  = sm + SM_P + warp * NTOK;
    float* myrh = sm + SM_R + warp * 28;
    float* myrw = myrh + 14;

    for (int r = warp; r < NTOK; r += 8) {
        const float* qsrc = base + (size_t)r * QKVN + h * HD;
        myq[lane]      = qsrc[lane];
        myq[lane + 32] = qsrc[lane + 32];
        __syncwarp();
        int ty = r / WIN, tx = r % WIN;
        if (lane < 28) {
            int kk = lane % 14;
            bool isw = lane >= 14;
            const float* rp = isw ? (relw + (size_t)(tx - kk + 13) * HD)
                                  : (relh + (size_t)(ty - kk + 13) * HD);
            float s = 0.f;
            #pragma unroll 8
            for (int d = 0; d < HD; d++) s += myq[d] * rp[d];
            (isw ? myrw : myrh)[kk] = s;
        }
        __syncwarp();

        float sc[7];
        float mx = -INFINITY;
        #pragma unroll
        for (int i = 0; i < 7; i++) {
            int j = lane + i * 32;
            float s = -INFINITY;
            if (j < NTOK) {
                float a = 0.f;
                const float* kr = Ks + j * KV_STRIDE;
                #pragma unroll 16
                for (int d = 0; d < HD; d++) a += myq[d] * kr[d];
                s = a * SCALE + myrh[j / WIN] + myrw[j % WIN];
            }
            sc[i] = s;
            mx = fmaxf(mx, s);
        }
        #pragma unroll
        for (int o = 16; o; o >>= 1) mx = fmaxf(mx, __shfl_xor_sync(0xffffffffu, mx, o));
        float sum = 0.f;
        #pragma unroll
        for (int i = 0; i < 7; i++) {
            int j = lane + i * 32;
            if (j < NTOK) {
                float e = __expf(sc[i] - mx);
                sum += e;
                myp[j] = e;
            }
        }
        #pragma unroll
        for (int o = 16; o; o >>= 1) sum += __shfl_xor_sync(0xffffffffu, sum, o);
        float inv = 1.f / sum;
        __syncwarp();

        float* orow = outp + ((size_t)w * NTOK + r) * DIM + h * HD;
        #pragma unroll
        for (int half = 0; half < 2; half++) {
            int d = lane + half * 32;
            float acc = 0.f;
            #pragma unroll 4
            for (int j = 0; j < NTOK; j++) acc += myp[j] * Vs[j * KV_STRIDE + d];
            orow[d] = acc * inv;
        }
        __syncwarp();
    }
}

// -------------------- launch -------------------------------------------------
extern "C" void kernel_launch(void* const* d_in, const int* in_sizes, int n_in,
                              void* d_out, int out_size)
{
    const float* x      = (const float*)d_in[0];
    const float* ln1_g  = (const float*)d_in[1];
    const float* ln1_b  = (const float*)d_in[2];
    const float* qkv_w  = (const float*)d_in[3];
    const float* qkv_b  = (const float*)d_in[4];
    const float* proj_w = (const float*)d_in[5];
    const float* proj_b = (const float*)d_in[6];
    const float* rel_h  = (const float*)d_in[7];
    const float* rel_w  = (const float*)d_in[8];
    const float* ln2_g  = (const float*)d_in[9];
    const float* ln2_b  = (const float*)d_in[10];
    const float* fc1_w  = (const float*)d_in[11];
    const float* fc1_b  = (const float*)d_in[12];
    const float* fc2_w  = (const float*)d_in[13];
    const float* fc2_b  = (const float*)d_in[14];
    float* out = (float*)d_out;

    float *p_xin, *p_qkv, *p_attn, *p_xres, *p_h2, *p_hid;
    cudaGetSymbolAddress((void**)&p_xin,  g_xin_ln);
    cudaGetSymbolAddress((void**)&p_qkv,  g_qkv);
    cudaGetSymbolAddress((void**)&p_attn, g_attn);
    cudaGetSymbolAddress((void**)&p_xres, g_xres);
    cudaGetSymbolAddress((void**)&p_h2,   g_h2);
    cudaGetSymbolAddress((void**)&p_hid,  g_hid);

    const int attn_smem = ATTN_SMEM_FLOATS * sizeof(float);
    cudaFuncSetAttribute(attn_kernel, cudaFuncAttributeMaxDynamicSharedMemorySize, attn_smem);

    // 1. LN1 + window partition (zero-padded)
    ln1_kernel<<<MROWS, 256>>>(x, ln1_g, ln1_b, p_xin);

    // 2. QKV GEMM: [9800,768] @ [768,2304]
    gemm_kernel<false, false, false><<<dim3(QKVN / 64, (MROWS + 63) / 64), 256>>>(
        p_xin, qkv_w, qkv_b, nullptr, p_qkv, MROWS, QKVN, DIM);

    // 3. attention per (window, head)
    attn_kernel<<<NWIN * HEADS, 256, attn_smem>>>(p_qkv, rel_h, rel_w, p_attn);

    // 4. proj GEMM with window gather + residual: x + attn @ proj_w
    gemm_kernel<true, false, true><<<dim3(DIM / 64, GROWS / 64), 256>>>(
        p_attn, proj_w, proj_b, x, p_xres, GROWS, DIM, DIM);

    // 5. LN2
    ln2_kernel<<<GROWS, 256>>>(p_xres, ln2_g, ln2_b, p_h2);

    // 6. fc1 + exact GELU: [8192,768] @ [768,3072]
    gemm_kernel<false, true, false><<<dim3(MLPH / 64, GROWS / 64), 256>>>(
        p_h2, fc1_w, fc1_b, nullptr, p_hid, GROWS, MLPH, DIM);

    // 7. fc2 + residual into d_out: [8192,3072] @ [3072,768]
    gemm_kernel<false, false, true><<<dim3(DIM / 64, GROWS / 64), 256>>>(
        p_hid, fc2_w, fc2_b, p_xres, out, GROWS, DIM, MLPH);
}

// round 3
// speedup vs baseline: 1.9425x; 1.9425x over previous
#include <cuda_runtime.h>
#include <cuda_bf16.h>
#include <math.h>
#include <stdint.h>

#define DIM   768
#define HEADS 12
#define HD    64
#define WIN   14
#define NTOK  196
#define NWIN  50
#define MROWS 9800
#define GROWS 8192
#define MLPH  3072
#define QKVN  2304
#define SCALE 0.125f

// -------------------- scratch (device globals; no allocation) ----------------
__device__ float g_xin_ln[MROWS * DIM];
__device__ float g_qkv  [MROWS * QKVN];
__device__ float g_attn [MROWS * DIM];
__device__ float g_xres [GROWS * DIM];
__device__ float g_h2   [GROWS * DIM];
__device__ float g_hid  [GROWS * MLPH];

// -------------------- helpers ------------------------------------------------
__device__ __forceinline__ float tf32r(float x) {
    uint32_t r;
    asm("cvt.rna.tf32.f32 %0, %1;" : "=r"(r) : "f"(x));
    return __uint_as_float(r);
}

__device__ __forceinline__ void blockReduce2(float& s, float& ss) {
    #pragma unroll
    for (int o = 16; o; o >>= 1) {
        s  += __shfl_xor_sync(0xffffffffu, s,  o);
        ss += __shfl_xor_sync(0xffffffffu, ss, o);
    }
    __shared__ float ra[8], rb[8];
    int warp = threadIdx.x >> 5, lane = threadIdx.x & 31;
    if (lane == 0) { ra[warp] = s; rb[warp] = ss; }
    __syncthreads();
    if (threadIdx.x == 0) {
        float t1 = 0.f, t2 = 0.f;
        #pragma unroll
        for (int i = 0; i < 8; i++) { t1 += ra[i]; t2 += rb[i]; }
        ra[0] = t1; rb[0] = t2;
    }
    __syncthreads();
    s = ra[0]; ss = rb[0];
}

// -------------------- LN1 + window partition (zero pad) ----------------------
__global__ __launch_bounds__(256) void ln1_kernel(
    const float* __restrict__ x, const float* __restrict__ g,
    const float* __restrict__ b, float* __restrict__ out)
{
    int t = blockIdx.x;
    int w  = t / NTOK, tk = t % NTOK;
    int img = w / 25, wy = (w % 25) / 5, wx = w % 5;
    int ty = tk / WIN, tx = tk % WIN;
    int y = wy * WIN + ty, xc = wx * WIN + tx;
    float* orow = out + (size_t)t * DIM;
    int tid = threadIdx.x;
    if (y >= 64 || xc >= 64) {
        orow[tid] = 0.f; orow[tid + 256] = 0.f; orow[tid + 512] = 0.f;
        return;
    }
    const float* row = x + (((size_t)img * 64 + y) * 64 + xc) * DIM;
    float v0 = row[tid], v1 = row[tid + 256], v2 = row[tid + 512];
    float s = v0 + v1 + v2, ss = v0 * v0 + v1 * v1 + v2 * v2;
    blockReduce2(s, ss);
    float mean = s * (1.f / DIM);
    float var  = ss * (1.f / DIM) - mean * mean;
    float rstd = rsqrtf(var + 1e-6f);
    orow[tid]       = (v0 - mean) * rstd * g[tid]       + b[tid];
    orow[tid + 256] = (v1 - mean) * rstd * g[tid + 256] + b[tid + 256];
    orow[tid + 512] = (v2 - mean) * rstd * g[tid + 512] + b[tid + 512];
}

__global__ __launch_bounds__(256) void ln2_kernel(
    const float* __restrict__ xin, const float* __restrict__ g,
    const float* __restrict__ b, float* __restrict__ out)
{
    int t = blockIdx.x;
    const float* row = xin + (size_t)t * DIM;
    float* orow = out + (size_t)t * DIM;
    int tid = threadIdx.x;
    float v0 = row[tid], v1 = row[tid + 256], v2 = row[tid + 512];
    float s = v0 + v1 + v2, ss = v0 * v0 + v1 * v1 + v2 * v2;
    blockReduce2(s, ss);
    float mean = s * (1.f / DIM);
    float var  = ss * (1.f / DIM) - mean * mean;
    float rstd = rsqrtf(var + 1e-6f);
    orow[tid]       = (v0 - mean) * rstd * g[tid]       + b[tid];
    orow[tid + 256] = (v1 - mean) * rstd * g[tid + 256] + b[tid + 256];
    orow[tid + 512] = (v2 - mean) * rstd * g[tid + 512] + b[tid + 512];
}

// -------------------- tf32 tensor-core GEMM ---------------------------------
// C[m,n] = A[m,:] @ B[:,n] + bias[n] (+gelu) (+res). 128x128x16 CTA tile,
// 8 warps of 64x32, m16n8k8 tf32 mma. A frags via ldmatrix, B via scalar LDS.
#define AST 20          // As row stride (floats): 16 k + 4 pad
#define BST 136         // Bs row stride (floats): 128 n + 8 pad

template<bool GATHER, bool GELU_ACT, bool RES>
__global__ __launch_bounds__(256) void gemm_tc(
    const float* __restrict__ A, const float* __restrict__ B,
    const float* __restrict__ bias, const float* __restrict__ Rs,
    float* __restrict__ C, int M, int Nn, int K)
{
    __shared__ float As[2][128 * AST];
    __shared__ float Bs[2][16 * BST];

    const int tid  = threadIdx.x;
    const int lane = tid & 31;
    const int warp = tid >> 5;
    const int wm = warp >> 2;      // 0..1 : 64-row slab
    const int wn = warp & 3;       // 0..3 : 32-col slab
    const int bm = blockIdx.y << 7;
    const int bn = blockIdx.x << 7;

    // ---- global load assignments ----
    const int am = tid >> 1;            // 0..127
    const int ak = (tid & 1) << 3;      // 0 or 8
    int gm = bm + am;
    int arow = gm < M ? gm : M - 1;
    if (GATHER) {
        int img = arow >> 12, rem = arow & 4095;
        int y = rem >> 6, xc = rem & 63;
        arow = (img * 25 + (y / WIN) * 5 + (xc / WIN)) * NTOK
             + (y % WIN) * WIN + (xc % WIN);
    }
    const float* aptr = A + (size_t)arow * K + ak;
    const int bk  = tid >> 4;           // 0..15
    const int bn0 = (tid & 15) << 3;    // 0..120
    const float* bptr = B + (size_t)bk * Nn + bn + bn0;

    const int a_st_off = am * AST + ak;
    const int b_st_off = bk * BST + bn0;

    // ---- fragment addresses ----
    uint32_t sA0 = (uint32_t)__cvta_generic_to_shared(&As[0][0]);
    // ldmatrix row/khalf per lane
    const int afr = (wm * 64 + (lane & 15)) * AST + (lane >> 4) * 4;
    // B fragment generic pointer offsets
    const int bfr = (lane & 3) * BST + wn * 32 + (lane >> 2);

    float acc[4][4][4];
    #pragma unroll
    for (int i = 0; i < 4; i++)
        #pragma unroll
        for (int j = 0; j < 4; j++)
            #pragma unroll
            for (int c = 0; c < 4; c++) acc[i][j][c] = 0.f;

    const int KT = K >> 4;

    // ---- prologue: load tile 0 ----
    float4 av0 = *(const float4*)(aptr);
    float4 av1 = *(const float4*)(aptr + 4);
    float4 bv0 = *(const float4*)(bptr);
    float4 bv1 = *(const float4*)(bptr + 4);
    {
        float* ap = &As[0][a_st_off];
        ap[0] = tf32r(av0.x); ap[1] = tf32r(av0.y); ap[2] = tf32r(av0.z); ap[3] = tf32r(av0.w);
        ap[4] = tf32r(av1.x); ap[5] = tf32r(av1.y); ap[6] = tf32r(av1.z); ap[7] = tf32r(av1.w);
        float* bp = &Bs[0][b_st_off];
        bp[0] = tf32r(bv0.x); bp[1] = tf32r(bv0.y); bp[2] = tf32r(bv0.z); bp[3] = tf32r(bv0.w);
        bp[4] = tf32r(bv1.x); bp[5] = tf32r(bv1.y); bp[6] = tf32r(bv1.z); bp[7] = tf32r(bv1.w);
    }
    __syncthreads();

    for (int kt = 0; kt < KT; kt++) {
        const int cur = kt & 1;
        const bool more = (kt + 1) < KT;
        if (more) {
            const float* ap = aptr + (kt + 1) * 16;
            av0 = *(const float4*)(ap);
            av1 = *(const float4*)(ap + 4);
            const float* bp = bptr + (size_t)(kt + 1) * 16 * Nn;
            bv0 = *(const float4*)(bp);
            bv1 = *(const float4*)(bp + 4);
        }

        // ---- compute from buffer cur ----
        uint32_t sAc = sA0 + cur * (128 * AST * 4);
        const float* Bc = &Bs[cur][0];
        #pragma unroll
        for (int kh = 0; kh < 2; kh++) {
            uint32_t a[4][4];
            #pragma unroll
            for (int mt = 0; mt < 4; mt++) {
                uint32_t addr = sAc + 4u * (afr + mt * (16 * AST) + kh * 8);
                asm volatile("ldmatrix.sync.aligned.m8n8.x4.shared.b16 {%0,%1,%2,%3}, [%4];"
                    : "=r"(a[mt][0]), "=r"(a[mt][1]), "=r"(a[mt][2]), "=r"(a[mt][3])
                    : "r"(addr));
            }
            uint32_t b0[4], b1[4];
            const float* bq = Bc + kh * 8 * BST + bfr;
            #pragma unroll
            for (int nt = 0; nt < 4; nt++) {
                b0[nt] = __float_as_uint(bq[nt * 8]);
                b1[nt] = __float_as_uint(bq[4 * BST + nt * 8]);
            }
            #pragma unroll
            for (int mt = 0; mt < 4; mt++)
                #pragma unroll
                for (int nt = 0; nt < 4; nt++) {
                    asm volatile(
                        "mma.sync.aligned.m16n8k8.row.col.f32.tf32.tf32.f32 "
                        "{%0,%1,%2,%3}, {%4,%5,%6,%7}, {%8,%9}, {%0,%1,%2,%3};"
                        : "+f"(acc[mt][nt][0]), "+f"(acc[mt][nt][1]),
                          "+f"(acc[mt][nt][2]), "+f"(acc[mt][nt][3])
                        : "r"(a[mt][0]), "r"(a[mt][1]), "r"(a[mt][2]), "r"(a[mt][3]),
                          "r"(b0[nt]), "r"(b1[nt]));
                }
        }

        // ---- store prefetched tile into next buffer ----
        if (more) {
            const int nxt = cur ^ 1;
            float* ap = &As[nxt][a_st_off];
            ap[0] = tf32r(av0.x); ap[1] = tf32r(av0.y); ap[2] = tf32r(av0.z); ap[3] = tf32r(av0.w);
            ap[4] = tf32r(av1.x); ap[5] = tf32r(av1.y); ap[6] = tf32r(av1.z); ap[7] = tf32r(av1.w);
            float* bp = &Bs[nxt][b_st_off];
            bp[0] = tf32r(bv0.x); bp[1] = tf32r(bv0.y); bp[2] = tf32r(bv0.z); bp[3] = tf32r(bv0.w);
            bp[4] = tf32r(bv1.x); bp[5] = tf32r(bv1.y); bp[6] = tf32r(bv1.z); bp[7] = tf32r(bv1.w);
        }
        __syncthreads();
    }

    // ---- epilogue ----
    const int rbase = bm + wm * 64 + (lane >> 2);
    const int cbase = bn + wn * 32 + (lane & 3) * 2;
    #pragma unroll
    for (int nt = 0; nt < 4; nt++) {
        int col = cbase + nt * 8;
        float bs0 = bias[col], bs1 = bias[col + 1];
        #pragma unroll
        for (int mt = 0; mt < 4; mt++) {
            int r0 = rbase + mt * 16;
            int r1 = r0 + 8;
            float v00 = acc[mt][nt][0] + bs0;
            float v01 = acc[mt][nt][1] + bs1;
            float v10 = acc[mt][nt][2] + bs0;
            float v11 = acc[mt][nt][3] + bs1;
            if (GELU_ACT) {
                v00 = 0.5f * v00 * (1.f + erff(v00 * 0.70710678f));
                v01 = 0.5f * v01 * (1.f + erff(v01 * 0.70710678f));
                v10 = 0.5f * v10 * (1.f + erff(v10 * 0.70710678f));
                v11 = 0.5f * v11 * (1.f + erff(v11 * 0.70710678f));
            }
            if (r0 < M) {
                if (RES) {
                    const float* rr = Rs + (size_t)r0 * Nn + col;
                    v00 += rr[0]; v01 += rr[1];
                }
                float2* cp = (float2*)(C + (size_t)r0 * Nn + col);
                *cp = make_float2(v00, v01);
            }
            if (r1 < M) {
                if (RES) {
                    const float* rr = Rs + (size_t)r1 * Nn + col;
                    v10 += rr[0]; v11 += rr[1];
                }
                float2* cp = (float2*)(C + (size_t)r1 * Nn + col);
                *cp = make_float2(v10, v11);
            }
        }
    }
}

// -------------------- attention: one CTA per (window, head) ------------------
#define KV_STRIDE 65
#define SM_K   0
#define SM_V   (NTOK * KV_STRIDE)
#define SM_Q   (2 * NTOK * KV_STRIDE)
#define SM_P   (SM_Q + 8 * 64)
#define SM_R   (SM_P + 8 * NTOK)
#define ATTN_SMEM_FLOATS (SM_R + 8 * 28)

__global__ __launch_bounds__(256) void attn_kernel(
    const float* __restrict__ qkv, const float* __restrict__ relh,
    const float* __restrict__ relw, float* __restrict__ outp)
{
    extern __shared__ float sm[];
    float* Ks = sm + SM_K;
    float* Vs = sm + SM_V;

    const int blk = blockIdx.x;
    const int w = blk / HEADS, h = blk % HEADS;
    const float* base = qkv + (size_t)w * NTOK * QKVN;
    const int tid = threadIdx.x, warp = tid >> 5, lane = tid & 31;

    for (int idx = tid; idx < NTOK * HD; idx += 256) {
        int j = idx >> 6, d = idx & 63;
        const float* src = base + (size_t)j * QKVN + h * HD + d;
        Ks[j * KV_STRIDE + d] = src[DIM];
        Vs[j * KV_STRIDE + d] = src[2 * DIM];
    }
    __syncthreads();

    float* myq  = sm + SM_Q + warp * 64;
    float* myp  = sm + SM_P + warp * NTOK;
    float* myrh = sm + SM_R + warp * 28;
    float* myrw = myrh + 14;

    for (int r = warp; r < NTOK; r += 8) {
        const float* qsrc = base + (size_t)r * QKVN + h * HD;
        myq[lane]      = qsrc[lane];
        myq[lane + 32] = qsrc[lane + 32];
        __syncwarp();
        int ty = r / WIN, tx = r % WIN;
        if (lane < 28) {
            int kk = lane % 14;
            bool isw = lane >= 14;
            const float* rp = isw ? (relw + (size_t)(tx - kk + 13) * HD)
                                  : (relh + (size_t)(ty - kk + 13) * HD);
            float s = 0.f;
            #pragma unroll 8
            for (int d = 0; d < HD; d++) s += myq[d] * rp[d];
            (isw ? myrw : myrh)[kk] = s;
        }
        __syncwarp();

        float sc[7];
        float mx = -INFINITY;
        #pragma unroll
        for (int i = 0; i < 7; i++) {
            int j = lane + i * 32;
            float s = -INFINITY;
            if (j < NTOK) {
                float a = 0.f;
                const float* kr = Ks + j * KV_STRIDE;
                #pragma unroll 16
                for (int d = 0; d < HD; d++) a += myq[d] * kr[d];
                s = a * SCALE + myrh[j / WIN] + myrw[j % WIN];
            }
            sc[i] = s;
            mx = fmaxf(mx, s);
        }
        #pragma unroll
        for (int o = 16; o; o >>= 1) mx = fmaxf(mx, __shfl_xor_sync(0xffffffffu, mx, o));
        float sum = 0.f;
        #pragma unroll
        for (int i = 0; i < 7; i++) {
            int j = lane + i * 32;
            if (j < NTOK) {
                float e = __expf(sc[i] - mx);
                sum += e;
                myp[j] = e;
            }
        }
        #pragma unroll
        for (int o = 16; o; o >>= 1) sum += __shfl_xor_sync(0xffffffffu, sum, o);
        float inv = 1.f / sum;
        __syncwarp();

        float* orow = outp + ((size_t)w * NTOK + r) * DIM + h * HD;
        #pragma unroll
        for (int half = 0; half < 2; half++) {
            int d = lane + half * 32;
            float acc = 0.f;
            #pragma unroll 4
            for (int j = 0; j < NTOK; j++) acc += myp[j] * Vs[j * KV_STRIDE + d];
            orow[d] = acc * inv;
        }
        __syncwarp();
    }
}

// -------------------- launch -------------------------------------------------
extern "C" void kernel_launch(void* const* d_in, const int* in_sizes, int n_in,
                              void* d_out, int out_size)
{
    const float* x      = (const float*)d_in[0];
    const float* ln1_g  = (const float*)d_in[1];
    const float* ln1_b  = (const float*)d_in[2];
    const float* qkv_w  = (const float*)d_in[3];
    const float* qkv_b  = (const float*)d_in[4];
    const float* proj_w = (const float*)d_in[5];
    const float* proj_b = (const float*)d_in[6];
    const float* rel_h  = (const float*)d_in[7];
    const float* rel_w  = (const float*)d_in[8];
    const float* ln2_g  = (const float*)d_in[9];
    const float* ln2_b  = (const float*)d_in[10];
    const float* fc1_w  = (const float*)d_in[11];
    const float* fc1_b  = (const float*)d_in[12];
    const float* fc2_w  = (const float*)d_in[13];
    const float* fc2_b  = (const float*)d_in[14];
    float* out = (float*)d_out;

    float *p_xin, *p_qkv, *p_attn, *p_xres, *p_h2, *p_hid;
    cudaGetSymbolAddress((void**)&p_xin,  g_xin_ln);
    cudaGetSymbolAddress((void**)&p_qkv,  g_qkv);
    cudaGetSymbolAddress((void**)&p_attn, g_attn);
    cudaGetSymbolAddress((void**)&p_xres, g_xres);
    cudaGetSymbolAddress((void**)&p_h2,   g_h2);
    cudaGetSymbolAddress((void**)&p_hid,  g_hid);

    const int attn_smem = ATTN_SMEM_FLOATS * sizeof(float);
    cudaFuncSetAttribute(attn_kernel, cudaFuncAttributeMaxDynamicSharedMemorySize, attn_smem);

    // 1. LN1 + window partition
    ln1_kernel<<<MROWS, 256>>>(x, ln1_g, ln1_b, p_xin);

    // 2. QKV GEMM [9800,768]x[768,2304]
    gemm_tc<false, false, false><<<dim3(QKVN / 128, (MROWS + 127) / 128), 256>>>(
        p_xin, qkv_w, qkv_b, nullptr, p_qkv, MROWS, QKVN, DIM);

    // 3. attention
    attn_kernel<<<NWIN * HEADS, 256, attn_smem>>>(p_qkv, rel_h, rel_w, p_attn);

    // 4. proj GEMM + gather + residual
    gemm_tc<true, false, true><<<dim3(DIM / 128, GROWS / 128), 256>>>(
        p_attn, proj_w, proj_b, x, p_xres, GROWS, DIM, DIM);

    // 5. LN2
    ln2_kernel<<<GROWS, 256>>>(p_xres, ln2_g, ln2_b, p_h2);

    // 6. fc1 + GELU
    gemm_tc<false, true, false><<<dim3(MLPH / 128, GROWS / 128), 256>>>(
        p_h2, fc1_w, fc1_b, nullptr, p_hid, GROWS, MLPH, DIM);

    // 7. fc2 + residual -> out
    gemm_tc<false, false, true><<<dim3(DIM / 128, GROWS / 128), 256>>>(
        p_hid, fc2_w, fc2_b, p_xres, out, GROWS, DIM, MLPH);
}

// round 4
// speedup vs baseline: 2.7429x; 1.4121x over previous
#include <cuda_runtime.h>
#include <cuda_bf16.h>
#include <math.h>
#include <stdint.h>

#define DIM   768
#define HEADS 12
#define HD    64
#define WIN   14
#define NTOK  196
#define NWIN  50
#define MROWS 9800
#define GROWS 8192
#define MLPH  3072
#define QKVN  2304
#define SCALE 0.125f

// -------------------- scratch (device globals; no allocation) ----------------
__device__ float g_xin_ln[MROWS * DIM];
__device__ float g_qkv  [MROWS * QKVN];
__device__ float g_attn [MROWS * DIM];
__device__ float g_xres [GROWS * DIM];
__device__ float g_h2   [GROWS * DIM];
__device__ float g_hid  [GROWS * MLPH];

// -------------------- helpers ------------------------------------------------
__device__ __forceinline__ void cp16(float* dst, const float* src) {
    uint32_t d = (uint32_t)__cvta_generic_to_shared(dst);
    asm volatile("cp.async.cg.shared.global [%0], [%1], 16;\n" :: "r"(d), "l"(src));
}
#define CP_COMMIT()  asm volatile("cp.async.commit_group;\n")
#define CP_WAIT2()   asm volatile("cp.async.wait_group 2;\n")

__device__ __forceinline__ void blockReduce2(float& s, float& ss) {
    #pragma unroll
    for (int o = 16; o; o >>= 1) {
        s  += __shfl_xor_sync(0xffffffffu, s,  o);
        ss += __shfl_xor_sync(0xffffffffu, ss, o);
    }
    __shared__ float ra[8], rb[8];
    int warp = threadIdx.x >> 5, lane = threadIdx.x & 31;
    if (lane == 0) { ra[warp] = s; rb[warp] = ss; }
    __syncthreads();
    if (threadIdx.x == 0) {
        float t1 = 0.f, t2 = 0.f;
        #pragma unroll
        for (int i = 0; i < 8; i++) { t1 += ra[i]; t2 += rb[i]; }
        ra[0] = t1; rb[0] = t2;
    }
    __syncthreads();
    s = ra[0]; ss = rb[0];
}

// -------------------- LN1 + window partition (zero pad) ----------------------
__global__ __launch_bounds__(256) void ln1_kernel(
    const float* __restrict__ x, const float* __restrict__ g,
    const float* __restrict__ b, float* __restrict__ out)
{
    int t = blockIdx.x;
    int w  = t / NTOK, tk = t % NTOK;
    int img = w / 25, wy = (w % 25) / 5, wx = w % 5;
    int ty = tk / WIN, tx = tk % WIN;
    int y = wy * WIN + ty, xc = wx * WIN + tx;
    float* orow = out + (size_t)t * DIM;
    int tid = threadIdx.x;
    if (y >= 64 || xc >= 64) {
        orow[tid] = 0.f; orow[tid + 256] = 0.f; orow[tid + 512] = 0.f;
        return;
    }
    const float* row = x + (((size_t)img * 64 + y) * 64 + xc) * DIM;
    float v0 = row[tid], v1 = row[tid + 256], v2 = row[tid + 512];
    float s = v0 + v1 + v2, ss = v0 * v0 + v1 * v1 + v2 * v2;
    blockReduce2(s, ss);
    float mean = s * (1.f / DIM);
    float var  = ss * (1.f / DIM) - mean * mean;
    float rstd = rsqrtf(var + 1e-6f);
    orow[tid]       = (v0 - mean) * rstd * g[tid]       + b[tid];
    orow[tid + 256] = (v1 - mean) * rstd * g[tid + 256] + b[tid + 256];
    orow[tid + 512] = (v2 - mean) * rstd * g[tid + 512] + b[tid + 512];
}

__global__ __launch_bounds__(256) void ln2_kernel(
    const float* __restrict__ xin, const float* __restrict__ g,
    const float* __restrict__ b, float* __restrict__ out)
{
    int t = blockIdx.x;
    const float* row = xin + (size_t)t * DIM;
    float* orow = out + (size_t)t * DIM;
    int tid = threadIdx.x;
    float v0 = row[tid], v1 = row[tid + 256], v2 = row[tid + 512];
    float s = v0 + v1 + v2, ss = v0 * v0 + v1 * v1 + v2 * v2;
    blockReduce2(s, ss);
    float mean = s * (1.f / DIM);
    float var  = ss * (1.f / DIM) - mean * mean;
    float rstd = rsqrtf(var + 1e-6f);
    orow[tid]       = (v0 - mean) * rstd * g[tid]       + b[tid];
    orow[tid + 256] = (v1 - mean) * rstd * g[tid + 256] + b[tid + 256];
    orow[tid + 512] = (v2 - mean) * rstd * g[tid + 512] + b[tid + 512];
}

// -------------------- tf32 tensor-core GEMM, cp.async 4-stage ----------------
#define AST 20              // As row stride (floats)
#define BST 136             // Bs row stride (floats)
#define STAGES 4
#define ASTAGE (128 * AST)  // floats per A stage
#define BSTAGE (16 * BST)   // floats per B stage
#define GEMM_SMEM_BYTES ((STAGES * (ASTAGE + BSTAGE)) * 4)

template<bool GATHER, bool GELU_ACT, bool RES>
__global__ __launch_bounds__(256) void gemm_tc(
    const float* __restrict__ A, const float* __restrict__ B,
    const float* __restrict__ bias, const float* __restrict__ Rs,
    float* __restrict__ C, int M, int Nn, int K)
{
    extern __shared__ float smem[];
    float* smA = smem;                       // STAGES * ASTAGE
    float* smB = smem + STAGES * ASTAGE;     // STAGES * BSTAGE

    const int tid  = threadIdx.x;
    const int lane = tid & 31;
    const int warp = tid >> 5;
    const int wm = warp >> 2;
    const int wn = warp & 3;
    const int bm = blockIdx.y << 7;
    const int bn = blockIdx.x << 7;

    // ---- global load assignments ----
    const int am = tid >> 1;            // 0..127
    const int ak = (tid & 1) << 3;      // 0 or 8
    int gm = bm + am;
    int arow = gm < M ? gm : M - 1;
    if (GATHER) {
        int img = arow >> 12, rem = arow & 4095;
        int y = rem >> 6, xc = rem & 63;
        arow = (img * 25 + (y / WIN) * 5 + (xc / WIN)) * NTOK
             + (y % WIN) * WIN + (xc % WIN);
    }
    const float* aptr = A + (size_t)arow * K + ak;
    const int bk  = tid >> 4;           // 0..15
    const int bn0 = (tid & 15) << 3;    // 0..120
    const float* bptr = B + (size_t)bk * Nn + bn + bn0;

    const int a_st_off = am * AST + ak;
    const int b_st_off = bk * BST + bn0;

    const int KT = K >> 4;

    // ---- fragment addressing ----
    uint32_t sA0 = (uint32_t)__cvta_generic_to_shared(smA);
    const int afr = (wm * 64 + (lane & 15)) * AST + (lane >> 4) * 4;
    const int bfr = (lane & 3) * BST + wn * 32 + (lane >> 2);

    float acc[4][4][4];
    #pragma unroll
    for (int i = 0; i < 4; i++)
        #pragma unroll
        for (int j = 0; j < 4; j++)
            #pragma unroll
            for (int c = 0; c < 4; c++) acc[i][j][c] = 0.f;

    // ---- prologue: issue tiles 0..STAGES-2 ----
    #pragma unroll
    for (int s = 0; s < STAGES - 1; s++) {
        if (s < KT) {
            const float* ap = aptr + s * 16;
            cp16(&smA[s * ASTAGE + a_st_off],     ap);
            cp16(&smA[s * ASTAGE + a_st_off + 4], ap + 4);
            const float* bp = bptr + (size_t)s * 16 * Nn;
            cp16(&smB[s * BSTAGE + b_st_off],     bp);
            cp16(&smB[s * BSTAGE + b_st_off + 4], bp + 4);
        }
        CP_COMMIT();
    }

    for (int kt = 0; kt < KT; kt++) {
        CP_WAIT2();
        __syncthreads();

        // issue tile kt+STAGES-1 into the stage computed last iteration
        {
            int nk = kt + STAGES - 1;
            if (nk < KT) {
                int s = nk & (STAGES - 1);
                const float* ap = aptr + nk * 16;
                cp16(&smA[s * ASTAGE + a_st_off],     ap);
                cp16(&smA[s * ASTAGE + a_st_off + 4], ap + 4);
                const float* bp = bptr + (size_t)nk * 16 * Nn;
                cp16(&smB[s * BSTAGE + b_st_off],     bp);
                cp16(&smB[s * BSTAGE + b_st_off + 4], bp + 4);
            }
            CP_COMMIT();
        }

        // ---- compute on stage kt % STAGES ----
        const int cur = kt & (STAGES - 1);
        uint32_t sAc = sA0 + (uint32_t)(cur * ASTAGE * 4);
        const float* Bc = smB + cur * BSTAGE;
        #pragma unroll
        for (int kh = 0; kh < 2; kh++) {
            uint32_t a[4][4];
            #pragma unroll
            for (int mt = 0; mt < 4; mt++) {
                uint32_t addr = sAc + 4u * (afr + mt * (16 * AST) + kh * 8);
                asm volatile("ldmatrix.sync.aligned.m8n8.x4.shared.b16 {%0,%1,%2,%3}, [%4];"
                    : "=r"(a[mt][0]), "=r"(a[mt][1]), "=r"(a[mt][2]), "=r"(a[mt][3])
                    : "r"(addr));
            }
            uint32_t b0[4], b1[4];
            const float* bq = Bc + kh * 8 * BST + bfr;
            #pragma unroll
            for (int nt = 0; nt < 4; nt++) {
                b0[nt] = __float_as_uint(bq[nt * 8]);
                b1[nt] = __float_as_uint(bq[4 * BST + nt * 8]);
            }
            #pragma unroll
            for (int mt = 0; mt < 4; mt++)
                #pragma unroll
                for (int nt = 0; nt < 4; nt++) {
                    asm volatile(
                        "mma.sync.aligned.m16n8k8.row.col.f32.tf32.tf32.f32 "
                        "{%0,%1,%2,%3}, {%4,%5,%6,%7}, {%8,%9}, {%0,%1,%2,%3};"
                        : "+f"(acc[mt][nt][0]), "+f"(acc[mt][nt][1]),
                          "+f"(acc[mt][nt][2]), "+f"(acc[mt][nt][3])
                        : "r"(a[mt][0]), "r"(a[mt][1]), "r"(a[mt][2]), "r"(a[mt][3]),
                          "r"(b0[nt]), "r"(b1[nt]));
                }
        }
    }

    // ---- epilogue ----
    const int rbase = bm + wm * 64 + (lane >> 2);
    const int cbase = bn + wn * 32 + (lane & 3) * 2;
    #pragma unroll
    for (int nt = 0; nt < 4; nt++) {
        int col = cbase + nt * 8;
        float bs0 = bias[col], bs1 = bias[col + 1];
        #pragma unroll
        for (int mt = 0; mt < 4; mt++) {
            int r0 = rbase + mt * 16;
            int r1 = r0 + 8;
            float v00 = acc[mt][nt][0] + bs0;
            float v01 = acc[mt][nt][1] + bs1;
            float v10 = acc[mt][nt][2] + bs0;
            float v11 = acc[mt][nt][3] + bs1;
            if (GELU_ACT) {
                v00 = 0.5f * v00 * (1.f + erff(v00 * 0.70710678f));
                v01 = 0.5f * v01 * (1.f + erff(v01 * 0.70710678f));
                v10 = 0.5f * v10 * (1.f + erff(v10 * 0.70710678f));
                v11 = 0.5f * v11 * (1.f + erff(v11 * 0.70710678f));
            }
            if (r0 < M) {
                if (RES) {
                    const float* rr = Rs + (size_t)r0 * Nn + col;
                    v00 += rr[0]; v01 += rr[1];
                }
                *(float2*)(C + (size_t)r0 * Nn + col) = make_float2(v00, v01);
            }
            if (r1 < M) {
                if (RES) {
                    const float* rr = Rs + (size_t)r1 * Nn + col;
                    v10 += rr[0]; v11 += rr[1];
                }
                *(float2*)(C + (size_t)r1 * Nn + col) = make_float2(v10, v11);
            }
        }
    }
}

// -------------------- attention: one CTA per (window, head) ------------------
#define KV_STRIDE 68
#define SM_K   0
#define SM_V   (NTOK * KV_STRIDE)
#define SM_P   (2 * NTOK * KV_STRIDE)
#define SM_R   (SM_P + 8 * NTOK)
#define ATTN_SMEM_FLOATS (SM_R + 8 * 28)

__global__ __launch_bounds__(256) void attn_kernel(
    const float* __restrict__ qkv, const float* __restrict__ relh,
    const float* __restrict__ relw, float* __restrict__ outp)
{
    extern __shared__ float sm[];
    float* Ks = sm + SM_K;
    float* Vs = sm + SM_V;

    const int blk = blockIdx.x;
    const int w = blk / HEADS, h = blk % HEADS;
    const float* base = qkv + (size_t)w * NTOK * QKVN;
    const int tid = threadIdx.x, warp = tid >> 5, lane = tid & 31;

    for (int idx = tid; idx < NTOK * HD; idx += 256) {
        int j = idx >> 6, d = idx & 63;
        const float* src = base + (size_t)j * QKVN + h * HD + d;
        Ks[j * KV_STRIDE + d] = src[DIM];
        Vs[j * KV_STRIDE + d] = src[2 * DIM];
    }
    __syncthreads();

    float* myp  = sm + SM_P + warp * NTOK;
    float* myrh = sm + SM_R + warp * 28;
    float* myrw = myrh + 14;

    for (int r = warp; r < NTOK; r += 8) {
        // q row into registers (broadcast loads)
        const float4* qsrc = (const float4*)(base + (size_t)r * QKVN + h * HD);
        float4 qv[16];
        #pragma unroll
        for (int d4 = 0; d4 < 16; d4++) qv[d4] = qsrc[d4];

        int ty = r / WIN, tx = r % WIN;
        if (lane < 28) {
            int kk = lane % 14;
            bool isw = lane >= 14;
            const float4* rp = (const float4*)(isw ? (relw + (size_t)(tx - kk + 13) * HD)
                                                   : (relh + (size_t)(ty - kk + 13) * HD));
            float s = 0.f;
            #pragma unroll
            for (int d4 = 0; d4 < 16; d4++) {
                float4 rv = rp[d4];
                s += qv[d4].x * rv.x + qv[d4].y * rv.y + qv[d4].z * rv.z + qv[d4].w * rv.w;
            }
            (isw ? myrw : myrh)[kk] = s;
        }
        __syncwarp();

        float sc[7];
        float mx = -INFINITY;
        #pragma unroll
        for (int i = 0; i < 7; i++) {
            int j = lane + i * 32;
            float s = -INFINITY;
            if (j < NTOK) {
                const float4* kr = (const float4*)(Ks + j * KV_STRIDE);
                float a = 0.f;
                #pragma unroll
                for (int d4 = 0; d4 < 16; d4++) {
                    float4 kv = kr[d4];
                    a += qv[d4].x * kv.x + qv[d4].y * kv.y + qv[d4].z * kv.z + qv[d4].w * kv.w;
                }
                s = a * SCALE + myrh[j / WIN] + myrw[j % WIN];
            }
            sc[i] = s;
            mx = fmaxf(mx, s);
        }
        #pragma unroll
        for (int o = 16; o; o >>= 1) mx = fmaxf(mx, __shfl_xor_sync(0xffffffffu, mx, o));
        float sum = 0.f;
        #pragma unroll
        for (int i = 0; i < 7; i++) {
            int j = lane + i * 32;
            if (j < NTOK) {
                float e = __expf(sc[i] - mx);
                sum += e;
                myp[j] = e;
            }
        }
        #pragma unroll
        for (int o = 16; o; o >>= 1) sum += __shfl_xor_sync(0xffffffffu, sum, o);
        float inv = 1.f / sum;
        __syncwarp();

        // PV: each lane accumulates dims (2*lane, 2*lane+1)
        float2 acc = make_float2(0.f, 0.f);
        const float2* vbase = (const float2*)(Vs) + lane;   // (Vs + lane*2)
        #pragma unroll 4
        for (int j = 0; j < NTOK; j++) {
            float p = myp[j];
            float2 vv = *(const float2*)(Vs + j * KV_STRIDE + lane * 2);
            acc.x += p * vv.x;
            acc.y += p * vv.y;
        }
        (void)vbase;
        float* orow = outp + ((size_t)w * NTOK + r) * DIM + h * HD;
        *(float2*)(orow + lane * 2) = make_float2(acc.x * inv, acc.y * inv);
        __syncwarp();
    }
}

// -------------------- launch -------------------------------------------------
extern "C" void kernel_launch(void* const* d_in, const int* in_sizes, int n_in,
                              void* d_out, int out_size)
{
    const float* x      = (const float*)d_in[0];
    const float* ln1_g  = (const float*)d_in[1];
    const float* ln1_b  = (const float*)d_in[2];
    const float* qkv_w  = (const float*)d_in[3];
    const float* qkv_b  = (const float*)d_in[4];
    const float* proj_w = (const float*)d_in[5];
    const float* proj_b = (const float*)d_in[6];
    const float* rel_h  = (const float*)d_in[7];
    const float* rel_w  = (const float*)d_in[8];
    const float* ln2_g  = (const float*)d_in[9];
    const float* ln2_b  = (const float*)d_in[10];
    const float* fc1_w  = (const float*)d_in[11];
    const float* fc1_b  = (const float*)d_in[12];
    const float* fc2_w  = (const float*)d_in[13];
    const float* fc2_b  = (const float*)d_in[14];
    float* out = (float*)d_out;

    float *p_xin, *p_qkv, *p_attn, *p_xres, *p_h2, *p_hid;
    cudaGetSymbolAddress((void**)&p_xin,  g_xin_ln);
    cudaGetSymbolAddress((void**)&p_qkv,  g_qkv);
    cudaGetSymbolAddress((void**)&p_attn, g_attn);
    cudaGetSymbolAddress((void**)&p_xres, g_xres);
    cudaGetSymbolAddress((void**)&p_h2,   g_h2);
    cudaGetSymbolAddress((void**)&p_hid,  g_hid);

    const int attn_smem = ATTN_SMEM_FLOATS * sizeof(float);
    cudaFuncSetAttribute(attn_kernel, cudaFuncAttributeMaxDynamicSharedMemorySize, attn_smem);
    cudaFuncSetAttribute((const void*)gemm_tc<false, false, false>,
                         cudaFuncAttributeMaxDynamicSharedMemorySize, GEMM_SMEM_BYTES);
    cudaFuncSetAttribute((const void*)gemm_tc<true, false, true>,
                         cudaFuncAttributeMaxDynamicSharedMemorySize, GEMM_SMEM_BYTES);
    cudaFuncSetAttribute((const void*)gemm_tc<false, true, false>,
                         cudaFuncAttributeMaxDynamicSharedMemorySize, GEMM_SMEM_BYTES);
    cudaFuncSetAttribute((const void*)gemm_tc<false, false, true>,
                         cudaFuncAttributeMaxDynamicSharedMemorySize, GEMM_SMEM_BYTES);

    // 1. LN1 + window partition
    ln1_kernel<<<MROWS, 256>>>(x, ln1_g, ln1_b, p_xin);

    // 2. QKV GEMM [9800,768]x[768,2304]
    gemm_tc<false, false, false><<<dim3(QKVN / 128, (MROWS + 127) / 128), 256, GEMM_SMEM_BYTES>>>(
        p_xin, qkv_w, qkv_b, nullptr, p_qkv, MROWS, QKVN, DIM);

    // 3. attention
    attn_kernel<<<NWIN * HEADS, 256, attn_smem>>>(p_qkv, rel_h, rel_w, p_attn);

    // 4. proj GEMM + gather + residual
    gemm_tc<true, false, true><<<dim3(DIM / 128, GROWS / 128), 256, GEMM_SMEM_BYTES>>>(
        p_attn, proj_w, proj_b, x, p_xres, GROWS, DIM, DIM);

    // 5. LN2
    ln2_kernel<<<GROWS, 256>>>(p_xres, ln2_g, ln2_b, p_h2);

    // 6. fc1 + GELU
    gemm_tc<false, true, false><<<dim3(MLPH / 128, GROWS / 128), 256, GEMM_SMEM_BYTES>>>(
        p_h2, fc1_w, fc1_b, nullptr, p_hid, GROWS, MLPH, DIM);

    // 7. fc2 + residual -> out
    gemm_tc<false, false, true><<<dim3(DIM / 128, GROWS / 128), 256, GEMM_SMEM_BYTES>>>(
        p_hid, fc2_w, fc2_b, p_xres, out, GROWS, DIM, MLPH);
}